// round 8
// baseline (speedup 1.0000x reference)
#include <cuda_runtime.h>
#include <cuda_fp16.h>
#include <math.h>
#include <stdint.h>

// Problem constants
#define BB 2
#define LL 4096
#define DD 512
#define HH 8
#define EE 64
#define CC 64
#define NC (LL/CC)         // 64
#define MM (BB*LL)         // 8192

// ---------------- scratch (device globals; no allocation) ----------------
__device__ float g_q[MM*DD];
__device__ float g_k[MM*DD];
__device__ float g_v[MM*DD];
__device__ float g_loglam[MM*HH];
__device__ float g_cum[MM*HH];
__device__ float g_state[(size_t)BB*HH*NC*EE*EE];
__device__ float g_zstate[BB*HH*NC*EE];
__device__ float g_proj[MM*DD];
__device__ __half g_xh[MM*DD];        // fp16 x (gemm0 A)
__device__ __half g_attnh[MM*DD];     // fp16 attention out (gemm1 A)
__device__ __half g_wqh[3*DD*DD];     // fp16 qkv_w
__device__ __half g_woh[DD*DD];       // fp16 out_w

// ---------------- helpers ----------------
__device__ __forceinline__ uint32_t f2tf32(float f) {
    uint32_t u;
    asm("cvt.rna.tf32.f32 %0, %1;" : "=r"(u) : "f"(f));
    return u;
}
__device__ __forceinline__ void mma_tf32(float c[4], const uint32_t a[4],
                                         uint32_t b0, uint32_t b1) {
    asm volatile(
        "mma.sync.aligned.m16n8k8.row.col.f32.tf32.tf32.f32 "
        "{%0,%1,%2,%3}, {%4,%5,%6,%7}, {%8,%9}, {%0,%1,%2,%3};"
        : "+f"(c[0]), "+f"(c[1]), "+f"(c[2]), "+f"(c[3])
        : "r"(a[0]), "r"(a[1]), "r"(a[2]), "r"(a[3]), "r"(b0), "r"(b1));
}
__device__ __forceinline__ void mma_f16(float c[4], uint32_t a0, uint32_t a1,
                                        uint32_t a2, uint32_t a3,
                                        uint32_t b0, uint32_t b1) {
    asm volatile(
        "mma.sync.aligned.m16n8k16.row.col.f32.f16.f16.f32 "
        "{%0,%1,%2,%3}, {%4,%5,%6,%7}, {%8,%9}, {%0,%1,%2,%3};"
        : "+f"(c[0]), "+f"(c[1]), "+f"(c[2]), "+f"(c[3])
        : "r"(a0), "r"(a1), "r"(a2), "r"(a3), "r"(b0), "r"(b1));
}
__device__ __forceinline__ void ldsm4(uint32_t& r0, uint32_t& r1,
                                      uint32_t& r2, uint32_t& r3, uint32_t addr) {
    asm volatile("ldmatrix.sync.aligned.m8n8.x4.shared.b16 {%0,%1,%2,%3}, [%4];"
                 : "=r"(r0), "=r"(r1), "=r"(r2), "=r"(r3) : "r"(addr));
}
__device__ __forceinline__ void cp_async16(uint32_t s, const void* g) {
    asm volatile("cp.async.ca.shared.global [%0], [%1], 16;" :: "r"(s), "l"(g));
}
__device__ __forceinline__ void cp_commit() { asm volatile("cp.async.commit_group;"); }
template<int N>
__device__ __forceinline__ void cp_wait() {
    asm volatile("cp.async.wait_group %0;" :: "n"(N));
}
__device__ __forceinline__ uint32_t smem_u32(const void* p) {
    return (uint32_t)__cvta_generic_to_shared(p);
}

// ---------------- fp16 tensor-core GEMM: C = A @ W^T + bias ----------------
// 128x128 block tile, K in 8 slabs of 64 halves (128B/row), double-buffered,
// ldmatrix.x4 fragment loads, mma.m16n8k16.f16 with fp32 accum.
// smem pitch 72 halves (144B): 16B-aligned, ldmatrix conflict-free.
#define HP 72
#define HSTG (128 * HP)               // halves per matrix per stage (9216)
#define GH_SMEM (4 * HSTG * 2)        // 2 stages x (A+B) x 2B = 73728

template<int MODE>
__global__ __launch_bounds__(256, 2)
void gemm_h(const float* __restrict__ bias)
{
    extern __shared__ __half hs[];
    const __half* A = (MODE == 0) ? g_xh : g_attnh;
    const __half* W = (MODE == 0) ? g_wqh : g_woh;

    const int tid  = threadIdx.x;
    const int w    = tid >> 5;
    const int lane = tid & 31;
    const int g    = lane >> 2;
    const int tig  = lane & 3;
    const int warpM = (w & 3) * 32;
    const int warpN = (w >> 2) * 64;
    const int bm = blockIdx.y * 128;
    const int bn = blockIdx.x * 128;

    float acc[2][8][4];
#pragma unroll
    for (int mt = 0; mt < 2; mt++)
#pragma unroll
        for (int nt = 0; nt < 8; nt++)
#pragma unroll
            for (int i = 0; i < 4; i++) acc[mt][nt][i] = 0.f;

    const uint32_t sb = smem_u32(hs);
    // ldmatrix per-thread row/koff decomposition
    const int rit = (lane & 7) + ((lane >> 3) & 1) * 8;   // row within 16
    const int kh8 = (lane >> 4) * 8;                      // k-half offset

    auto load_stage = [&](int s) {
        const uint32_t abase = sb + (uint32_t)((s & 1) * 2 * HSTG) * 2u;
        const uint32_t bbase = abase + (uint32_t)HSTG * 2u;
#pragma unroll
        for (int i = 0; i < 4; i++) {
            const int o = tid + i * 256;        // 0..1023
            const int row = o >> 3;
            const int c = o & 7;                // 16B chunk (8 halves)
            cp_async16(abase + (uint32_t)(row * HP + c * 8) * 2u,
                       A + (size_t)(bm + row) * DD + s * 64 + c * 8);
            cp_async16(bbase + (uint32_t)(row * HP + c * 8) * 2u,
                       W + (size_t)(bn + row) * DD + s * 64 + c * 8);
        }
        cp_commit();
    };

    load_stage(0);
    load_stage(1);

    const int NS = DD / 64;   // 8
    for (int s = 0; s < NS; s++) {
        if (s + 1 < NS) cp_wait<1>(); else cp_wait<0>();
        __syncthreads();
        const uint32_t abase = sb + (uint32_t)((s & 1) * 2 * HSTG) * 2u;
        const uint32_t bbase = abase + (uint32_t)HSTG * 2u;

#pragma unroll
        for (int kk = 0; kk < 4; kk++) {
            const uint32_t koff = (uint32_t)(kk * 16 + kh8) * 2u;
            uint32_t a[2][4];
#pragma unroll
            for (int mt = 0; mt < 2; mt++)
                ldsm4(a[mt][0], a[mt][1], a[mt][2], a[mt][3],
                      abase + (uint32_t)((warpM + mt * 16 + rit) * HP) * 2u + koff);
#pragma unroll
            for (int ng = 0; ng < 4; ng++) {
                uint32_t r0, r1, r2, r3;
                ldsm4(r0, r1, r2, r3,
                      bbase + (uint32_t)((warpN + ng * 16 + rit) * HP) * 2u + koff);
#pragma unroll
                for (int mt = 0; mt < 2; mt++) {
                    mma_f16(acc[mt][2 * ng    ], a[mt][0], a[mt][1], a[mt][2], a[mt][3], r0, r2);
                    mma_f16(acc[mt][2 * ng + 1], a[mt][0], a[mt][1], a[mt][2], a[mt][3], r1, r3);
                }
            }
        }
        __syncthreads();
        if (s + 2 < NS) load_stage(s + 2);
    }

    // ---------------- epilogue ----------------
    const int nbase = bn + warpN;
    if (MODE == 0) {
        const int sec = nbase >> 9;          // 0:q 1:k 2:v
        const int colbase = nbase & 511;
        const int h = colbase >> 6;
        float* dst = (sec == 0) ? g_q : (sec == 1) ? g_k : g_v;
        float fac[2][2];
#pragma unroll
        for (int mt = 0; mt < 2; mt++)
#pragma unroll
            for (int rh = 0; rh < 2; rh++) {
                const int m = bm + warpM + mt * 16 + g + rh * 8;
                const float c = g_cum[m * HH + h];
                fac[mt][rh] = (sec == 0) ? __expf(c) * 0.125f
                            : (sec == 1) ? __expf(-c) : 1.f;
            }
#pragma unroll
        for (int mt = 0; mt < 2; mt++)
#pragma unroll
            for (int nt = 0; nt < 8; nt++) {
                const int ng = nbase + nt * 8 + tig * 2;
                const float b0 = bias[ng], b1 = bias[ng + 1];
                const int coln = colbase + nt * 8 + tig * 2;
#pragma unroll
                for (int rh = 0; rh < 2; rh++) {
                    const int m = bm + warpM + mt * 16 + g + rh * 8;
                    float v0 = acc[mt][nt][2 * rh    ] + b0;
                    float v1 = acc[mt][nt][2 * rh + 1] + b1;
                    if (sec < 2) {
                        v0 = (v0 > 0.f) ? (v0 + 1.f) : __expf(v0);
                        v1 = (v1 > 0.f) ? (v1 + 1.f) : __expf(v1);
                        v0 *= fac[mt][rh];
                        v1 *= fac[mt][rh];
                    }
                    float2 o; o.x = v0; o.y = v1;
                    *(float2*)(dst + (size_t)m * DD + coln) = o;
                }
            }
    } else {
#pragma unroll
        for (int mt = 0; mt < 2; mt++)
#pragma unroll
            for (int nt = 0; nt < 8; nt++) {
                const int ng = nbase + nt * 8 + tig * 2;
                const float b0 = bias[ng], b1 = bias[ng + 1];
#pragma unroll
                for (int rh = 0; rh < 2; rh++) {
                    const int m = bm + warpM + mt * 16 + g + rh * 8;
                    float2 o;
                    o.x = acc[mt][nt][2 * rh    ] + b0;
                    o.y = acc[mt][nt][2 * rh + 1] + b1;
                    *(float2*)(g_proj + (size_t)m * DD + ng) = o;
                }
            }
    }
}

// ---------------- convert all GEMM operands to fp16 ----------------
__global__ __launch_bounds__(256)
void roundh_kernel(const float* __restrict__ qkv_w, const float* __restrict__ out_w,
                   const float* __restrict__ x)
{
    const int u = blockIdx.x * 256 + threadIdx.x;    // 8-float unit
    const int NQ = 3 * DD * DD / 8;
    const int NO = DD * DD / 8;
    const float4* src;
    __half2* dst;
    int idx;
    if (u < NQ)           { src = (const float4*)qkv_w; dst = (__half2*)g_wqh; idx = u; }
    else if (u < NQ + NO) { src = (const float4*)out_w; dst = (__half2*)g_woh; idx = u - NQ; }
    else                  { src = (const float4*)x;     dst = (__half2*)g_xh;  idx = u - NQ - NO; }
    float4 v0 = src[2 * idx], v1 = src[2 * idx + 1];
    dst[4 * idx + 0] = __floats2half2_rn(v0.x, v0.y);
    dst[4 * idx + 1] = __floats2half2_rn(v0.z, v0.w);
    dst[4 * idx + 2] = __floats2half2_rn(v1.x, v1.y);
    dst[4 * idx + 3] = __floats2half2_rn(v1.z, v1.w);
}

// ---------------- decay logits ----------------
__global__ __launch_bounds__(256)
void decay_kernel(const float* __restrict__ x, const float* __restrict__ dw,
                  const float* __restrict__ db)
{
    const int m = blockIdx.x;
    const int h = threadIdx.x >> 5;
    const int lane = threadIdx.x & 31;
    const float* xr = x + (size_t)m * DD;
    const float* wr = dw + h * DD;
    float s = 0.f;
    for (int k = lane * 4; k < DD; k += 128) {
        float4 xv = *(const float4*)(xr + k);
        float4 wv = *(const float4*)(wr + k);
        s += xv.x * wv.x + xv.y * wv.y + xv.z * wv.z + xv.w * wv.w;
    }
#pragma unroll
    for (int off = 16; off; off >>= 1) s += __shfl_xor_sync(0xffffffffu, s, off);
    if (lane == 0) {
        float logit = s + db[h];
        float lam = 0.9f + 0.1f / (1.f + expf(-logit));
        g_loglam[m * HH + h] = logf(lam);
    }
}

// ---------------- cumsum of log-lambda along L ----------------
__global__ __launch_bounds__(256)
void cumsum_kernel()
{
    const int b = blockIdx.x >> 3;
    const int h = blockIdx.x & 7;
    const int tid = threadIdx.x;
    float vals[16];
    float s = 0.f;
    const int base = (b * LL + tid * 16) * HH + h;
#pragma unroll
    for (int i = 0; i < 16; i++) { s += g_loglam[base + i * HH]; vals[i] = s; }
    __shared__ float ts[256];
    ts[tid] = s;
    __syncthreads();
    for (int off = 1; off < 256; off <<= 1) {
        float v = (tid >= off) ? ts[tid - off] : 0.f;
        __syncthreads();
        ts[tid] += v;
        __syncthreads();
    }
    const float prev = (tid > 0) ? ts[tid - 1] : 0.f;
#pragma unroll
    for (int i = 0; i < 16; i++) {
        float c = prev + vals[i];
        c = fminf(50.f, fmaxf(-50.f, c));
        g_cum[base + i * HH] = c;
    }
}

// ---------------- per-chunk transposed KV state + k-sum (tf32 mma) ----------
#define TP 65
__global__ __launch_bounds__(128)
void chunkstate_mma()
{
    __shared__ float kT[64 * TP];
    __shared__ float vT[64 * TP];
    const int c = blockIdx.x & (NC - 1);
    const int h = (blockIdx.x >> 6) & 7;
    const int b = blockIdx.x >> 9;
    const int bh = b * HH + h;
    const int tid = threadIdx.x;
    const int w = tid >> 5;
    const int lane = tid & 31;
    const int g = lane >> 2;
    const int tig = lane & 3;
    const int rowbase = b * LL + c * CC;

#pragma unroll
    for (int it = 0; it < 8; it++) {
        int idx4 = tid + it * 128;
        int t = idx4 >> 4;
        int e4 = (idx4 & 15) << 2;
        size_t gidx = (size_t)(rowbase + t) * DD + h * EE + e4;
        float4 kv = *(const float4*)(g_k + gidx);
        float4 vv = *(const float4*)(g_v + gidx);
        kT[(e4 + 0) * TP + t] = kv.x; kT[(e4 + 1) * TP + t] = kv.y;
        kT[(e4 + 2) * TP + t] = kv.z; kT[(e4 + 3) * TP + t] = kv.w;
        vT[(e4 + 0) * TP + t] = vv.x; vT[(e4 + 1) * TP + t] = vv.y;
        vT[(e4 + 2) * TP + t] = vv.z; vT[(e4 + 3) * TP + t] = vv.w;
    }
    __syncthreads();

    const int f0 = w * 16;
    float acc[8][4];
#pragma unroll
    for (int nt = 0; nt < 8; nt++)
#pragma unroll
        for (int i = 0; i < 4; i++) acc[nt][i] = 0.f;

#pragma unroll
    for (int kk = 0; kk < 8; kk++) {
        const int k0 = kk * 8;
        uint32_t a[4];
        a[0] = f2tf32(vT[(f0 + g    ) * TP + k0 + tig    ]);
        a[1] = f2tf32(vT[(f0 + g + 8) * TP + k0 + tig    ]);
        a[2] = f2tf32(vT[(f0 + g    ) * TP + k0 + tig + 4]);
        a[3] = f2tf32(vT[(f0 + g + 8) * TP + k0 + tig + 4]);
#pragma unroll
        for (int nt = 0; nt < 8; nt++) {
            uint32_t b0 = f2tf32(kT[(nt * 8 + g) * TP + k0 + tig    ]);
            uint32_t b1 = f2tf32(kT[(nt * 8 + g) * TP + k0 + tig + 4]);
            mma_tf32(acc[nt], a, b0, b1);
        }
    }

    const size_t sbx = ((size_t)bh * NC + c) * (EE * EE);
#pragma unroll
    for (int nt = 0; nt < 8; nt++) {
        const int e0 = nt * 8 + tig * 2;
        float2 s0; s0.x = acc[nt][0]; s0.y = acc[nt][1];
        float2 s1; s1.x = acc[nt][2]; s1.y = acc[nt][3];
        *(float2*)(g_state + sbx + (f0 + g    ) * EE + e0) = s0;
        *(float2*)(g_state + sbx + (f0 + g + 8) * EE + e0) = s1;
    }
    if (tid < 64) {
        float z = 0.f;
#pragma unroll 8
        for (int t = 0; t < CC; t++) z += kT[tid * TP + t];
        g_zstate[(bh * NC + c) * EE + tid] = z;
    }
}

// ---------------- exclusive scan over chunks ----------------
__global__ __launch_bounds__(256)
void statescan_kernel()
{
    const int bh = blockIdx.x >> 4;
    const int split = blockIdx.x & 15;
    const int elem = split * 256 + threadIdx.x;
    size_t base = (size_t)bh * NC * EE * EE + elem;
    float run = 0.f;
#pragma unroll 4
    for (int c = 0; c < NC; c++) {
        float v = g_state[base + (size_t)c * EE * EE];
        g_state[base + (size_t)c * EE * EE] = run;
        run += v;
    }
    if (split == 0 && threadIdx.x < 64) {
        size_t zb = (size_t)bh * NC * EE + threadIdx.x;
        float r = 0.f;
        for (int c = 0; c < NC; c++) {
            float v = g_zstate[zb + (size_t)c * EE];
            g_zstate[zb + (size_t)c * EE] = r;
            r += v;
        }
    }
}

// ---------------- intra-chunk attention (tf32 mma) ----------------
#define IP 68
#define OQ 0
#define OK (64*IP)
#define OP (2*64*IP)
#define OS (3*64*IP)
#define OV (4*64*IP)
#define OZ (OV + 64*TP)
#define ODEN (OZ + 64)
#define ISMF (ODEN + 64)

__global__ __launch_bounds__(256)
void intra_mma()
{
    extern __shared__ float sm[];
    const int c = blockIdx.x & (NC - 1);
    const int h = (blockIdx.x >> 6) & 7;
    const int b = blockIdx.x >> 9;
    const int bh = b * HH + h;
    const int tid = threadIdx.x;
    const int w = tid >> 5;
    const int lane = tid & 31;
    const int g = lane >> 2;
    const int tig = lane & 3;
    const int rowbase = b * LL + c * CC;
    const size_t sbx = ((size_t)bh * NC + c) * (EE * EE);

#pragma unroll
    for (int it = 0; it < 4; it++) {
        int idx4 = tid + it * 256;
        int t = idx4 >> 4;
        int e4 = (idx4 & 15) << 2;
        size_t gidx = (size_t)(rowbase + t) * DD + h * EE + e4;
        *(float4*)&sm[OQ + t * IP + e4] = *(const float4*)(g_q + gidx);
        *(float4*)&sm[OK + t * IP + e4] = *(const float4*)(g_k + gidx);
        float4 vv = *(const float4*)(g_v + gidx);
        sm[OV + (e4 + 0) * TP + t] = vv.x; sm[OV + (e4 + 1) * TP + t] = vv.y;
        sm[OV + (e4 + 2) * TP + t] = vv.z; sm[OV + (e4 + 3) * TP + t] = vv.w;
        *(float4*)&sm[OS + t * IP + e4] = *(const float4*)(g_state + sbx + idx4 * 4);
    }
    if (tid < 64) sm[OZ + tid] = g_zstate[(bh * NC + c) * EE + tid];
    __syncthreads();

    const int wm = (w & 3) * 16;
    const int wn = (w >> 2) * 32;

    // phase 1: P = q k^T, causal mask
    {
        float pacc[4][4];
#pragma unroll
        for (int nt = 0; nt < 4; nt++)
#pragma unroll
            for (int i = 0; i < 4; i++) pacc[nt][i] = 0.f;
#pragma unroll
        for (int kk = 0; kk < 8; kk++) {
            const int k0 = kk * 8;
            uint32_t a[4];
            a[0] = f2tf32(sm[OQ + (wm + g    ) * IP + k0 + tig    ]);
            a[1] = f2tf32(sm[OQ + (wm + g + 8) * IP + k0 + tig    ]);
            a[2] = f2tf32(sm[OQ + (wm + g    ) * IP + k0 + tig + 4]);
            a[3] = f2tf32(sm[OQ + (wm + g + 8) * IP + k0 + tig + 4]);
#pragma unroll
            for (int nt = 0; nt < 4; nt++) {
                uint32_t b0 = f2tf32(sm[OK + (wn + nt * 8 + g) * IP + k0 + tig    ]);
                uint32_t b1 = f2tf32(sm[OK + (wn + nt * 8 + g) * IP + k0 + tig + 4]);
                mma_tf32(pacc[nt], a, b0, b1);
            }
        }
#pragma unroll
        for (int nt = 0; nt < 4; nt++) {
            const int scol = wn + nt * 8 + tig * 2;
            const int r0 = wm + g, r1 = wm + g + 8;
            float2 p0, p1;
            p0.x = (scol     <= r0) ? pacc[nt][0] : 0.f;
            p0.y = (scol + 1 <= r0) ? pacc[nt][1] : 0.f;
            p1.x = (scol     <= r1) ? pacc[nt][2] : 0.f;
            p1.y = (scol + 1 <= r1) ? pacc[nt][3] : 0.f;
            *(float2*)&sm[OP + r0 * IP + scol] = p0;
            *(float2*)&sm[OP + r1 * IP + scol] = p1;
        }
    }
    __syncthreads();

    // phase 2: denominators
    if (tid < 64) {
        const int t = tid;
        float s = 0.f;
#pragma unroll 8
        for (int s2 = 0; s2 < CC; s2++) s += sm[OP + t * IP + s2];
#pragma unroll 8
        for (int e = 0; e < EE; e++) s += sm[OQ + t * IP + e] * sm[OZ + e];
        sm[ODEN + t] = 1.f / (s + 1e-6f);
    }
    __syncthreads();

    // phase 3: num = P @ v + q @ S_T; out = num * rden -> fp16 g_attnh
    {
        float acc[4][4];
#pragma unroll
        for (int nt = 0; nt < 4; nt++)
#pragma unroll
            for (int i = 0; i < 4; i++) acc[nt][i] = 0.f;

#pragma unroll
        for (int kk = 0; kk < 8; kk++) {
            const int k0 = kk * 8;
            uint32_t a[4];
            a[0] = f2tf32(sm[OP + (wm + g    ) * IP + k0 + tig    ]);
            a[1] = f2tf32(sm[OP + (wm + g + 8) * IP + k0 + tig    ]);
            a[2] = f2tf32(sm[OP + (wm + g    ) * IP + k0 + tig + 4]);
            a[3] = f2tf32(sm[OP + (wm + g + 8) * IP + k0 + tig + 4]);
#pragma unroll
            for (int nt = 0; nt < 4; nt++) {
                uint32_t b0 = f2tf32(sm[OV + (wn + nt * 8 + g) * TP + k0 + tig    ]);
                uint32_t b1 = f2tf32(sm[OV + (wn + nt * 8 + g) * TP + k0 + tig + 4]);
                mma_tf32(acc[nt], a, b0, b1);
            }
        }
#pragma unroll
        for (int kk = 0; kk < 8; kk++) {
            const int k0 = kk * 8;
            uint32_t a[4];
            a[0] = f2tf32(sm[OQ + (wm + g    ) * IP + k0 + tig    ]);
            a[1] = f2tf32(sm[OQ + (wm + g + 8) * IP + k0 + tig    ]);
            a[2] = f2tf32(sm[OQ + (wm + g    ) * IP + k0 + tig + 4]);
            a[3] = f2tf32(sm[OQ + (wm + g + 8) * IP + k0 + tig + 4]);
#pragma unroll
            for (int nt = 0; nt < 4; nt++) {
                uint32_t b0 = f2tf32(sm[OS + (wn + nt * 8 + g) * IP + k0 + tig    ]);
                uint32_t b1 = f2tf32(sm[OS + (wn + nt * 8 + g) * IP + k0 + tig + 4]);
                mma_tf32(acc[nt], a, b0, b1);
            }
        }

        const float rd0 = sm[ODEN + wm + g];
        const float rd1 = sm[ODEN + wm + g + 8];
#pragma unroll
        for (int nt = 0; nt < 4; nt++) {
            const int colb = h * EE + wn + nt * 8 + tig * 2;
            *(__half2*)(g_attnh + (size_t)(rowbase + wm + g    ) * DD + colb) =
                __floats2half2_rn(acc[nt][0] * rd0, acc[nt][1] * rd0);
            *(__half2*)(g_attnh + (size_t)(rowbase + wm + g + 8) * DD + colb) =
                __floats2half2_rn(acc[nt][2] * rd1, acc[nt][3] * rd1);
        }
    }
}

// ---------------- RMSNorm ----------------
__global__ __launch_bounds__(128)
void rmsnorm_kernel(const float* __restrict__ scale, float* __restrict__ out)
{
    const int m = blockIdx.x;
    const int tid = threadIdx.x;
    float4 v = *(const float4*)(g_proj + (size_t)m * DD + tid * 4);
    float ss = v.x * v.x + v.y * v.y + v.z * v.z + v.w * v.w;
#pragma unroll
    for (int off = 16; off; off >>= 1) ss += __shfl_xor_sync(0xffffffffu, ss, off);
    __shared__ float ws[4];
    if ((tid & 31) == 0) ws[tid >> 5] = ss;
    __syncthreads();
    float tot = ws[0] + ws[1] + ws[2] + ws[3];
    float rn = rsqrtf(tot * (1.f / DD) + 1e-8f);
    float4 sc = *(const float4*)(scale + tid * 4);
    float4 o;
    o.x = v.x * rn * sc.x; o.y = v.y * rn * sc.y;
    o.z = v.z * rn * sc.z; o.w = v.w * rn * sc.w;
    *(float4*)(out + (size_t)m * DD + tid * 4) = o;
}

// ---------------- launch ----------------
extern "C" void kernel_launch(void* const* d_in, const int* in_sizes, int n_in,
                              void* d_out, int out_size)
{
    const float* x          = (const float*)d_in[0];
    const float* qkv_w      = (const float*)d_in[1];
    const float* qkv_b      = (const float*)d_in[2];
    const float* out_w      = (const float*)d_in[3];
    const float* out_b      = (const float*)d_in[4];
    const float* decay_w    = (const float*)d_in[5];
    const float* decay_b    = (const float*)d_in[6];
    const float* norm_scale = (const float*)d_in[7];
    float* out = (float*)d_out;

    cudaFuncSetAttribute(gemm_h<0>, cudaFuncAttributeMaxDynamicSharedMemorySize, GH_SMEM);
    cudaFuncSetAttribute(gemm_h<1>, cudaFuncAttributeMaxDynamicSharedMemorySize, GH_SMEM);
    const int ism = ISMF * (int)sizeof(float);
    cudaFuncSetAttribute(intra_mma, cudaFuncAttributeMaxDynamicSharedMemorySize, ism);

    decay_kernel<<<MM, 256>>>(x, decay_w, decay_b);            // #1
    cumsum_kernel<<<BB * HH, 256>>>();                         // #2
    roundh_kernel<<<2560, 256>>>(qkv_w, out_w, x);             // #3
    gemm_h<0><<<dim3(12, 64), 256, GH_SMEM>>>(qkv_b);          // #4  <- ncu capture slot
    chunkstate_mma<<<BB * HH * NC, 128>>>();                   // #5
    statescan_kernel<<<BB * HH * 16, 256>>>();                 // #6
    intra_mma<<<BB * HH * NC, 256, ism>>>();                   // #7
    gemm_h<1><<<dim3(4, 64), 256, GH_SMEM>>>(out_b);           // #8
    rmsnorm_kernel<<<MM, 128>>>(norm_scale, out);              // #9
}

// round 11
// speedup vs baseline: 1.6076x; 1.6076x over previous
#include <cuda_runtime.h>
#include <cuda_fp16.h>
#include <math.h>
#include <stdint.h>

// Problem constants
#define BB 2
#define LL 4096
#define DD 512
#define HH 8
#define EE 64
#define CC 64
#define NC (LL/CC)         // 64
#define MM (BB*LL)         // 8192

// ---------------- scratch (device globals; no allocation) ----------------
__device__ float g_q[MM*DD];
__device__ float g_k[MM*DD];
__device__ float g_v[MM*DD];
__device__ float g_loglam[MM*HH];
__device__ float g_cum[MM*HH];
__device__ float g_state[(size_t)BB*HH*NC*EE*EE];
__device__ float g_zstate[BB*HH*NC*EE];
__device__ float g_proj[MM*DD];
__device__ __half g_xh[MM*DD];        // fp16 x (gemm0 A)
__device__ __half g_attnh[MM*DD];     // fp16 attention out (gemm1 A)
__device__ __half g_wqh[3*DD*DD];     // fp16 qkv_w
__device__ __half g_woh[DD*DD];       // fp16 out_w

// ---------------- helpers ----------------
__device__ __forceinline__ uint32_t f2tf32(float f) {
    uint32_t u;
    asm("cvt.rna.tf32.f32 %0, %1;" : "=r"(u) : "f"(f));
    return u;
}
__device__ __forceinline__ void mma_tf32(float c[4], const uint32_t a[4],
                                         uint32_t b0, uint32_t b1) {
    asm volatile(
        "mma.sync.aligned.m16n8k8.row.col.f32.tf32.tf32.f32 "
        "{%0,%1,%2,%3}, {%4,%5,%6,%7}, {%8,%9}, {%0,%1,%2,%3};"
        : "+f"(c[0]), "+f"(c[1]), "+f"(c[2]), "+f"(c[3])
        : "r"(a[0]), "r"(a[1]), "r"(a[2]), "r"(a[3]), "r"(b0), "r"(b1));
}
__device__ __forceinline__ void mma_f16(float c[4], uint32_t a0, uint32_t a1,
                                        uint32_t a2, uint32_t a3,
                                        uint32_t b0, uint32_t b1) {
    asm volatile(
        "mma.sync.aligned.m16n8k16.row.col.f32.f16.f16.f32 "
        "{%0,%1,%2,%3}, {%4,%5,%6,%7}, {%8,%9}, {%0,%1,%2,%3};"
        : "+f"(c[0]), "+f"(c[1]), "+f"(c[2]), "+f"(c[3])
        : "r"(a0), "r"(a1), "r"(a2), "r"(a3), "r"(b0), "r"(b1));
}
__device__ __forceinline__ void ldsm4(uint32_t& r0, uint32_t& r1,
                                      uint32_t& r2, uint32_t& r3, uint32_t addr) {
    asm volatile("ldmatrix.sync.aligned.m8n8.x4.shared.b16 {%0,%1,%2,%3}, [%4];"
                 : "=r"(r0), "=r"(r1), "=r"(r2), "=r"(r3) : "r"(addr));
}
__device__ __forceinline__ void cp_async16(uint32_t s, const void* g) {
    asm volatile("cp.async.ca.shared.global [%0], [%1], 16;" :: "r"(s), "l"(g));
}
__device__ __forceinline__ void cp_commit() { asm volatile("cp.async.commit_group;"); }
template<int N>
__device__ __forceinline__ void cp_wait() {
    asm volatile("cp.async.wait_group %0;" :: "n"(N));
}
__device__ __forceinline__ uint32_t smem_u32(const void* p) {
    return (uint32_t)__cvta_generic_to_shared(p);
}

// ---------------- fp16 tensor-core GEMM: C = A @ W^T + bias ----------------
#define HP 72
#define HSTG (128 * HP)               // halves per matrix per stage
#define GH_SMEM (4 * HSTG * 2)        // 73728 B

template<int MODE>
__global__ __launch_bounds__(256, 2)
void gemm_h(const float* __restrict__ bias)
{
    extern __shared__ __half hs[];
    const __half* A = (MODE == 0) ? g_xh : g_attnh;
    const __half* W = (MODE == 0) ? g_wqh : g_woh;

    const int tid  = threadIdx.x;
    const int w    = tid >> 5;
    const int lane = tid & 31;
    const int g    = lane >> 2;
    const int tig  = lane & 3;
    const int warpM = (w & 3) * 32;
    const int warpN = (w >> 2) * 64;
    const int bm = blockIdx.y * 128;
    const int bn = blockIdx.x * 128;

    float acc[2][8][4];
#pragma unroll
    for (int mt = 0; mt < 2; mt++)
#pragma unroll
        for (int nt = 0; nt < 8; nt++)
#pragma unroll
            for (int i = 0; i < 4; i++) acc[mt][nt][i] = 0.f;

    const uint32_t sb = smem_u32(hs);
    const int rit = (lane & 7) + ((lane >> 3) & 1) * 8;
    const int kh8 = (lane >> 4) * 8;

    auto load_stage = [&](int s) {
        const uint32_t abase = sb + (uint32_t)((s & 1) * 2 * HSTG) * 2u;
        const uint32_t bbase = abase + (uint32_t)HSTG * 2u;
#pragma unroll
        for (int i = 0; i < 4; i++) {
            const int o = tid + i * 256;
            const int row = o >> 3;
            const int c = o & 7;
            cp_async16(abase + (uint32_t)(row * HP + c * 8) * 2u,
                       A + (size_t)(bm + row) * DD + s * 64 + c * 8);
            cp_async16(bbase + (uint32_t)(row * HP + c * 8) * 2u,
                       W + (size_t)(bn + row) * DD + s * 64 + c * 8);
        }
        cp_commit();
    };

    load_stage(0);
    load_stage(1);

    // hoisted per-warp ldmatrix row bases (bytes), two buffers
    uint32_t aRow[2][2], bRow[2][4];
#pragma unroll
    for (int bsel = 0; bsel < 2; bsel++) {
        const uint32_t abase = sb + (uint32_t)(bsel * 2 * HSTG) * 2u;
        const uint32_t bbase = abase + (uint32_t)HSTG * 2u;
#pragma unroll
        for (int mt = 0; mt < 2; mt++)
            aRow[bsel][mt] = abase + (uint32_t)((warpM + mt * 16 + rit) * HP + kh8) * 2u;
#pragma unroll
        for (int ng = 0; ng < 4; ng++)
            bRow[bsel][ng] = bbase + (uint32_t)((warpN + ng * 16 + rit) * HP + kh8) * 2u;
    }

    const int NS = DD / 64;   // 8
    for (int s = 0; s < NS; s++) {
        if (s + 1 < NS) cp_wait<1>(); else cp_wait<0>();
        __syncthreads();
        const int bsel = s & 1;
#pragma unroll
        for (int kk = 0; kk < 4; kk++) {
            const uint32_t koff = (uint32_t)(kk * 16) * 2u;
            uint32_t a[2][4];
#pragma unroll
            for (int mt = 0; mt < 2; mt++)
                ldsm4(a[mt][0], a[mt][1], a[mt][2], a[mt][3], aRow[bsel][mt] + koff);
#pragma unroll
            for (int ng = 0; ng < 4; ng++) {
                uint32_t r0, r1, r2, r3;
                ldsm4(r0, r1, r2, r3, bRow[bsel][ng] + koff);
#pragma unroll
                for (int mt = 0; mt < 2; mt++) {
                    mma_f16(acc[mt][2 * ng    ], a[mt][0], a[mt][1], a[mt][2], a[mt][3], r0, r2);
                    mma_f16(acc[mt][2 * ng + 1], a[mt][0], a[mt][1], a[mt][2], a[mt][3], r1, r3);
                }
            }
        }
        __syncthreads();
        if (s + 2 < NS) load_stage(s + 2);
    }

    // ---------------- epilogue ----------------
    const int nbase = bn + warpN;
    if (MODE == 0) {
        const int sec = nbase >> 9;
        const int colbase = nbase & 511;
        const int h = colbase >> 6;
        float* dst = (sec == 0) ? g_q : (sec == 1) ? g_k : g_v;
        float fac[2][2];
#pragma unroll
        for (int mt = 0; mt < 2; mt++)
#pragma unroll
            for (int rh = 0; rh < 2; rh++) {
                const int m = bm + warpM + mt * 16 + g + rh * 8;
                const float c = g_cum[m * HH + h];
                fac[mt][rh] = (sec == 0) ? __expf(c) * 0.125f
                            : (sec == 1) ? __expf(-c) : 1.f;
            }
#pragma unroll
        for (int mt = 0; mt < 2; mt++)
#pragma unroll
            for (int nt = 0; nt < 8; nt++) {
                const int ng = nbase + nt * 8 + tig * 2;
                const float b0 = bias[ng], b1 = bias[ng + 1];
                const int coln = colbase + nt * 8 + tig * 2;
#pragma unroll
                for (int rh = 0; rh < 2; rh++) {
                    const int m = bm + warpM + mt * 16 + g + rh * 8;
                    float v0 = acc[mt][nt][2 * rh    ] + b0;
                    float v1 = acc[mt][nt][2 * rh + 1] + b1;
                    if (sec < 2) {
                        v0 = (v0 > 0.f) ? (v0 + 1.f) : __expf(v0);
                        v1 = (v1 > 0.f) ? (v1 + 1.f) : __expf(v1);
                        v0 *= fac[mt][rh];
                        v1 *= fac[mt][rh];
                    }
                    float2 o; o.x = v0; o.y = v1;
                    *(float2*)(dst + (size_t)m * DD + coln) = o;
                }
            }
    } else {
#pragma unroll
        for (int mt = 0; mt < 2; mt++)
#pragma unroll
            for (int nt = 0; nt < 8; nt++) {
                const int ng = nbase + nt * 8 + tig * 2;
                const float b0 = bias[ng], b1 = bias[ng + 1];
#pragma unroll
                for (int rh = 0; rh < 2; rh++) {
                    const int m = bm + warpM + mt * 16 + g + rh * 8;
                    float2 o;
                    o.x = acc[mt][nt][2 * rh    ] + b0;
                    o.y = acc[mt][nt][2 * rh + 1] + b1;
                    *(float2*)(g_proj + (size_t)m * DD + ng) = o;
                }
            }
    }
}

// ---------------- prep: fp16 conversion (blocks 0..2559) + decay logits ------
#define NCVT 2560
__global__ __launch_bounds__(256)
void prep_kernel(const float* __restrict__ qkv_w, const float* __restrict__ out_w,
                 const float* __restrict__ x, const float* __restrict__ dw,
                 const float* __restrict__ db)
{
    if (blockIdx.x < NCVT) {
        const int u = blockIdx.x * 256 + threadIdx.x;    // 8-float unit
        const int NQ = 3 * DD * DD / 8;
        const int NO = DD * DD / 8;
        const float4* src;
        __half2* dst;
        int idx;
        if (u < NQ)           { src = (const float4*)qkv_w; dst = (__half2*)g_wqh; idx = u; }
        else if (u < NQ + NO) { src = (const float4*)out_w; dst = (__half2*)g_woh; idx = u - NQ; }
        else                  { src = (const float4*)x;     dst = (__half2*)g_xh;  idx = u - NQ - NO; }
        float4 v0 = src[2 * idx], v1 = src[2 * idx + 1];
        dst[4 * idx + 0] = __floats2half2_rn(v0.x, v0.y);
        dst[4 * idx + 1] = __floats2half2_rn(v0.z, v0.w);
        dst[4 * idx + 2] = __floats2half2_rn(v1.x, v1.y);
        dst[4 * idx + 3] = __floats2half2_rn(v1.z, v1.w);
        return;
    }
    const int m = blockIdx.x - NCVT;
    const int h = threadIdx.x >> 5;
    const int lane = threadIdx.x & 31;
    const float* xr = x + (size_t)m * DD;
    const float* wr = dw + h * DD;
    float s = 0.f;
    for (int k = lane * 4; k < DD; k += 128) {
        float4 xv = *(const float4*)(xr + k);
        float4 wv = *(const float4*)(wr + k);
        s += xv.x * wv.x + xv.y * wv.y + xv.z * wv.z + xv.w * wv.w;
    }
#pragma unroll
    for (int off = 16; off; off >>= 1) s += __shfl_xor_sync(0xffffffffu, s, off);
    if (lane == 0) {
        float logit = s + db[h];
        float lam = 0.9f + 0.1f / (1.f + expf(-logit));
        g_loglam[m * HH + h] = logf(lam);
    }
}

// ---------------- cumsum of log-lambda along L ----------------
__global__ __launch_bounds__(256)
void cumsum_kernel()
{
    const int b = blockIdx.x >> 3;
    const int h = blockIdx.x & 7;
    const int tid = threadIdx.x;
    float vals[16];
    float s = 0.f;
    const int base = (b * LL + tid * 16) * HH + h;
#pragma unroll
    for (int i = 0; i < 16; i++) { s += g_loglam[base + i * HH]; vals[i] = s; }
    __shared__ float ts[256];
    ts[tid] = s;
    __syncthreads();
    for (int off = 1; off < 256; off <<= 1) {
        float v = (tid >= off) ? ts[tid - off] : 0.f;
        __syncthreads();
        ts[tid] += v;
        __syncthreads();
    }
    const float prev = (tid > 0) ? ts[tid - 1] : 0.f;
#pragma unroll
    for (int i = 0; i < 16; i++) {
        float c = prev + vals[i];
        c = fminf(50.f, fmaxf(-50.f, c));
        g_cum[base + i * HH] = c;
    }
}

// ---------------- per-chunk transposed KV state + k-sum (tf32 mma) ----------
#define TP 65
__global__ __launch_bounds__(128)
void chunkstate_mma()
{
    __shared__ float kT[64 * TP];
    __shared__ float vT[64 * TP];
    const int c = blockIdx.x & (NC - 1);
    const int h = (blockIdx.x >> 6) & 7;
    const int b = blockIdx.x >> 9;
    const int bh = b * HH + h;
    const int tid = threadIdx.x;
    const int w = tid >> 5;
    const int lane = tid & 31;
    const int g = lane >> 2;
    const int tig = lane & 3;
    const int rowbase = b * LL + c * CC;

#pragma unroll
    for (int it = 0; it < 8; it++) {
        int idx4 = tid + it * 128;
        int t = idx4 >> 4;
        int e4 = (idx4 & 15) << 2;
        size_t gidx = (size_t)(rowbase + t) * DD + h * EE + e4;
        float4 kv = *(const float4*)(g_k + gidx);
        float4 vv = *(const float4*)(g_v + gidx);
        kT[(e4 + 0) * TP + t] = kv.x; kT[(e4 + 1) * TP + t] = kv.y;
        kT[(e4 + 2) * TP + t] = kv.z; kT[(e4 + 3) * TP + t] = kv.w;
        vT[(e4 + 0) * TP + t] = vv.x; vT[(e4 + 1) * TP + t] = vv.y;
        vT[(e4 + 2) * TP + t] = vv.z; vT[(e4 + 3) * TP + t] = vv.w;
    }
    __syncthreads();

    const int f0 = w * 16;
    float acc[8][4];
#pragma unroll
    for (int nt = 0; nt < 8; nt++)
#pragma unroll
        for (int i = 0; i < 4; i++) acc[nt][i] = 0.f;

#pragma unroll
    for (int kk = 0; kk < 8; kk++) {
        const int k0 = kk * 8;
        uint32_t a[4];
        a[0] = f2tf32(vT[(f0 + g    ) * TP + k0 + tig    ]);
        a[1] = f2tf32(vT[(f0 + g + 8) * TP + k0 + tig    ]);
        a[2] = f2tf32(vT[(f0 + g    ) * TP + k0 + tig + 4]);
        a[3] = f2tf32(vT[(f0 + g + 8) * TP + k0 + tig + 4]);
#pragma unroll
        for (int nt = 0; nt < 8; nt++) {
            uint32_t b0 = f2tf32(kT[(nt * 8 + g) * TP + k0 + tig    ]);
            uint32_t b1 = f2tf32(kT[(nt * 8 + g) * TP + k0 + tig + 4]);
            mma_tf32(acc[nt], a, b0, b1);
        }
    }

    const size_t sbx = ((size_t)bh * NC + c) * (EE * EE);
#pragma unroll
    for (int nt = 0; nt < 8; nt++) {
        const int e0 = nt * 8 + tig * 2;
        float2 s0; s0.x = acc[nt][0]; s0.y = acc[nt][1];
        float2 s1; s1.x = acc[nt][2]; s1.y = acc[nt][3];
        *(float2*)(g_state + sbx + (f0 + g    ) * EE + e0) = s0;
        *(float2*)(g_state + sbx + (f0 + g + 8) * EE + e0) = s1;
    }
    if (tid < 64) {
        float z = 0.f;
#pragma unroll 8
        for (int t = 0; t < CC; t++) z += kT[tid * TP + t];
        g_zstate[(bh * NC + c) * EE + tid] = z;
    }
}

// ---------------- exclusive scan over chunks ----------------
__global__ __launch_bounds__(256)
void statescan_kernel()
{
    const int bh = blockIdx.x >> 4;
    const int split = blockIdx.x & 15;
    const int elem = split * 256 + threadIdx.x;
    size_t base = (size_t)bh * NC * EE * EE + elem;
    float run = 0.f;
#pragma unroll 4
    for (int c = 0; c < NC; c++) {
        float v = g_state[base + (size_t)c * EE * EE];
        g_state[base + (size_t)c * EE * EE] = run;
        run += v;
    }
    if (split == 0 && threadIdx.x < 64) {
        size_t zb = (size_t)bh * NC * EE + threadIdx.x;
        float r = 0.f;
        for (int c = 0; c < NC; c++) {
            float v = g_zstate[zb + (size_t)c * EE];
            g_zstate[zb + (size_t)c * EE] = r;
            r += v;
        }
    }
}

// ---------------- intra-chunk attention (tf32 mma) ----------------
#define IP 68
#define OQ 0
#define OK (64*IP)
#define OP (2*64*IP)
#define OS (3*64*IP)
#define OV (4*64*IP)
#define OZ (OV + 64*TP)
#define ODEN (OZ + 64)
#define ISMF (ODEN + 64)

__global__ __launch_bounds__(256)
void intra_mma()
{
    extern __shared__ float sm[];
    const int c = blockIdx.x & (NC - 1);
    const int h = (blockIdx.x >> 6) & 7;
    const int b = blockIdx.x >> 9;
    const int bh = b * HH + h;
    const int tid = threadIdx.x;
    const int w = tid >> 5;
    const int lane = tid & 31;
    const int g = lane >> 2;
    const int tig = lane & 3;
    const int rowbase = b * LL + c * CC;
    const size_t sbx = ((size_t)bh * NC + c) * (EE * EE);

#pragma unroll
    for (int it = 0; it < 4; it++) {
        int idx4 = tid + it * 256;
        int t = idx4 >> 4;
        int e4 = (idx4 & 15) << 2;
        size_t gidx = (size_t)(rowbase + t) * DD + h * EE + e4;
        *(float4*)&sm[OQ + t * IP + e4] = *(const float4*)(g_q + gidx);
        *(float4*)&sm[OK + t * IP + e4] = *(const float4*)(g_k + gidx);
        float4 vv = *(const float4*)(g_v + gidx);
        sm[OV + (e4 + 0) * TP + t] = vv.x; sm[OV + (e4 + 1) * TP + t] = vv.y;
        sm[OV + (e4 + 2) * TP + t] = vv.z; sm[OV + (e4 + 3) * TP + t] = vv.w;
        *(float4*)&sm[OS + t * IP + e4] = *(const float4*)(g_state + sbx + idx4 * 4);
    }
    if (tid < 64) sm[OZ + tid] = g_zstate[(bh * NC + c) * EE + tid];
    __syncthreads();

    const int wm = (w & 3) * 16;
    const int wn = (w >> 2) * 32;

    // phase 1: P = q k^T, causal mask; fully-masked warp tiles skip the MMAs
    if (wn > wm + 15) {
        const float2 z2 = make_float2(0.f, 0.f);
#pragma unroll
        for (int nt = 0; nt < 4; nt++) {
            const int scol = wn + nt * 8 + tig * 2;
            *(float2*)&sm[OP + (wm + g    ) * IP + scol] = z2;
            *(float2*)&sm[OP + (wm + g + 8) * IP + scol] = z2;
        }
    } else {
        float pacc[4][4];
#pragma unroll
        for (int nt = 0; nt < 4; nt++)
#pragma unroll
            for (int i = 0; i < 4; i++) pacc[nt][i] = 0.f;
#pragma unroll
        for (int kk = 0; kk < 8; kk++) {
            const int k0 = kk * 8;
            uint32_t a[4];
            a[0] = f2tf32(sm[OQ + (wm + g    ) * IP + k0 + tig    ]);
            a[1] = f2tf32(sm[OQ + (wm + g + 8) * IP + k0 + tig    ]);
            a[2] = f2tf32(sm[OQ + (wm + g    ) * IP + k0 + tig + 4]);
            a[3] = f2tf32(sm[OQ + (wm + g + 8) * IP + k0 + tig + 4]);
#pragma unroll
            for (int nt = 0; nt < 4; nt++) {
                uint32_t b0 = f2tf32(sm[OK + (wn + nt * 8 + g) * IP + k0 + tig    ]);
                uint32_t b1 = f2tf32(sm[OK + (wn + nt * 8 + g) * IP + k0 + tig + 4]);
                mma_tf32(pacc[nt], a, b0, b1);
            }
        }
#pragma unroll
        for (int nt = 0; nt < 4; nt++) {
            const int scol = wn + nt * 8 + tig * 2;
            const int r0 = wm + g, r1 = wm + g + 8;
            float2 p0, p1;
            p0.x = (scol     <= r0) ? pacc[nt][0] : 0.f;
            p0.y = (scol + 1 <= r0) ? pacc[nt][1] : 0.f;
            p1.x = (scol     <= r1) ? pacc[nt][2] : 0.f;
            p1.y = (scol + 1 <= r1) ? pacc[nt][3] : 0.f;
            *(float2*)&sm[OP + r0 * IP + scol] = p0;
            *(float2*)&sm[OP + r1 * IP + scol] = p1;
        }
    }
    __syncthreads();

    // phase 2: denominators
    if (tid < 64) {
        const int t = tid;
        float s = 0.f;
#pragma unroll 8
        for (int s2 = 0; s2 < CC; s2++) s += sm[OP + t * IP + s2];
#pragma unroll 8
        for (int e = 0; e < EE; e++) s += sm[OQ + t * IP + e] * sm[OZ + e];
        sm[ODEN + t] = 1.f / (s + 1e-6f);
    }
    __syncthreads();

    // phase 3: num = P @ v + q @ S_T; out = num * rden -> fp16 g_attnh
    {
        float acc[4][4];
#pragma unroll
        for (int nt = 0; nt < 4; nt++)
#pragma unroll
            for (int i = 0; i < 4; i++) acc[nt][i] = 0.f;

#pragma unroll
        for (int kk = 0; kk < 8; kk++) {
            const int k0 = kk * 8;
            uint32_t a[4];
            a[0] = f2tf32(sm[OP + (wm + g    ) * IP + k0 + tig    ]);
            a[1] = f2tf32(sm[OP + (wm + g + 8) * IP + k0 + tig    ]);
            a[2] = f2tf32(sm[OP + (wm + g    ) * IP + k0 + tig + 4]);
            a[3] = f2tf32(sm[OP + (wm + g + 8) * IP + k0 + tig + 4]);
#pragma unroll
            for (int nt = 0; nt < 4; nt++) {
                uint32_t b0 = f2tf32(sm[OV + (wn + nt * 8 + g) * TP + k0 + tig    ]);
                uint32_t b1 = f2tf32(sm[OV + (wn + nt * 8 + g) * TP + k0 + tig + 4]);
                mma_tf32(acc[nt], a, b0, b1);
            }
        }
#pragma unroll
        for (int kk = 0; kk < 8; kk++) {
            const int k0 = kk * 8;
            uint32_t a[4];
            a[0] = f2tf32(sm[OQ + (wm + g    ) * IP + k0 + tig    ]);
            a[1] = f2tf32(sm[OQ + (wm + g + 8) * IP + k0 + tig    ]);
            a[2] = f2tf32(sm[OQ + (wm + g    ) * IP + k0 + tig + 4]);
            a[3] = f2tf32(sm[OQ + (wm + g + 8) * IP + k0 + tig + 4]);
#pragma unroll
            for (int nt = 0; nt < 4; nt++) {
                uint32_t b0 = f2tf32(sm[OS + (wn + nt * 8 + g) * IP + k0 + tig    ]);
                uint32_t b1 = f2tf32(sm[OS + (wn + nt * 8 + g) * IP + k0 + tig + 4]);
                mma_tf32(acc[nt], a, b0, b1);
            }
        }

        const float rd0 = sm[ODEN + wm + g];
        const float rd1 = sm[ODEN + wm + g + 8];
#pragma unroll
        for (int nt = 0; nt < 4; nt++) {
            const int colb = h * EE + wn + nt * 8 + tig * 2;
            *(__half2*)(g_attnh + (size_t)(rowbase + wm + g    ) * DD + colb) =
                __floats2half2_rn(acc[nt][0] * rd0, acc[nt][1] * rd0);
            *(__half2*)(g_attnh + (size_t)(rowbase + wm + g + 8) * DD + colb) =
                __floats2half2_rn(acc[nt][2] * rd1, acc[nt][3] * rd1);
        }
    }
}

// ---------------- RMSNorm ----------------
__global__ __launch_bounds__(128)
void rmsnorm_kernel(const float* __restrict__ scale, float* __restrict__ out)
{
    const int m = blockIdx.x;
    const int tid = threadIdx.x;
    float4 v = *(const float4*)(g_proj + (size_t)m * DD + tid * 4);
    float ss = v.x * v.x + v.y * v.y + v.z * v.z + v.w * v.w;
#pragma unroll
    for (int off = 16; off; off >>= 1) ss += __shfl_xor_sync(0xffffffffu, ss, off);
    __shared__ float ws[4];
    if ((tid & 31) == 0) ws[tid >> 5] = ss;
    __syncthreads();
    float tot = ws[0] + ws[1] + ws[2] + ws[3];
    float rn = rsqrtf(tot * (1.f / DD) + 1e-8f);
    float4 sc = *(const float4*)(scale + tid * 4);
    float4 o;
    o.x = v.x * rn * sc.x; o.y = v.y * rn * sc.y;
    o.z = v.z * rn * sc.z; o.w = v.w * rn * sc.w;
    *(float4*)(out + (size_t)m * DD + tid * 4) = o;
}

// ---------------- launch ----------------
extern "C" void kernel_launch(void* const* d_in, const int* in_sizes, int n_in,
                              void* d_out, int out_size)
{
    const float* x          = (const float*)d_in[0];
    const float* qkv_w      = (const float*)d_in[1];
    const float* qkv_b      = (const float*)d_in[2];
    const float* out_w      = (const float*)d_in[3];
    const float* out_b      = (const float*)d_in[4];
    const float* decay_w    = (const float*)d_in[5];
    const float* decay_b    = (const float*)d_in[6];
    const float* norm_scale = (const float*)d_in[7];
    float* out = (float*)d_out;

    cudaFuncSetAttribute(gemm_h<0>, cudaFuncAttributeMaxDynamicSharedMemorySize, GH_SMEM);
    cudaFuncSetAttribute(gemm_h<1>, cudaFuncAttributeMaxDynamicSharedMemorySize, GH_SMEM);
    const int ism = ISMF * (int)sizeof(float);
    cudaFuncSetAttribute(intra_mma, cudaFuncAttributeMaxDynamicSharedMemorySize, ism);

    prep_kernel<<<NCVT + MM, 256>>>(qkv_w, out_w, x, decay_w, decay_b);  // #1
    cumsum_kernel<<<BB * HH, 256>>>();                                   // #2
    gemm_h<0><<<dim3(12, 64), 256, GH_SMEM>>>(qkv_b);                    // #3
    chunkstate_mma<<<BB * HH * NC, 128>>>();                             // #4 <- capture
    statescan_kernel<<<BB * HH * 16, 256>>>();                           // #5
    intra_mma<<<BB * HH * NC, 256, ism>>>();                             // #6
    gemm_h<1><<<dim3(4, 64), 256, GH_SMEM>>>(out_b);                     // #7
    rmsnorm_kernel<<<MM, 128>>>(norm_scale, out);                        // #8
}

// round 12
// speedup vs baseline: 1.7119x; 1.0648x over previous
#include <cuda_runtime.h>
#include <cuda_fp16.h>
#include <math.h>
#include <stdint.h>

// Problem constants
#define BB 2
#define LL 4096
#define DD 512
#define HH 8
#define EE 64
#define CC 64
#define NC (LL/CC)         // 64
#define MM (BB*LL)         // 8192

// ---------------- scratch (device globals; no allocation) ----------------
__device__ float g_q[MM*DD];
__device__ float g_k[MM*DD];
__device__ float g_v[MM*DD];
__device__ float g_loglam[MM*HH];
__device__ float g_cum[MM*HH];
__device__ float g_state[(size_t)BB*HH*NC*EE*EE];
__device__ float g_zstate[BB*HH*NC*EE];
__device__ float g_proj[MM*DD];
__device__ __half g_xh[MM*DD];        // fp16 x (gemm0 A)
__device__ __half g_attnh[MM*DD];     // fp16 attention out (gemm1 A)
__device__ __half g_wqh[3*DD*DD];     // fp16 qkv_w
__device__ __half g_woh[DD*DD];       // fp16 out_w

// ---------------- helpers ----------------
__device__ __forceinline__ uint32_t f2tf32(float f) {
    uint32_t u;
    asm("cvt.rna.tf32.f32 %0, %1;" : "=r"(u) : "f"(f));
    return u;
}
__device__ __forceinline__ void mma_tf32(float c[4], const uint32_t a[4],
                                         uint32_t b0, uint32_t b1) {
    asm volatile(
        "mma.sync.aligned.m16n8k8.row.col.f32.tf32.tf32.f32 "
        "{%0,%1,%2,%3}, {%4,%5,%6,%7}, {%8,%9}, {%0,%1,%2,%3};"
        : "+f"(c[0]), "+f"(c[1]), "+f"(c[2]), "+f"(c[3])
        : "r"(a[0]), "r"(a[1]), "r"(a[2]), "r"(a[3]), "r"(b0), "r"(b1));
}
__device__ __forceinline__ void mma_f16(float c[4], uint32_t a0, uint32_t a1,
                                        uint32_t a2, uint32_t a3,
                                        uint32_t b0, uint32_t b1) {
    asm volatile(
        "mma.sync.aligned.m16n8k16.row.col.f32.f16.f16.f32 "
        "{%0,%1,%2,%3}, {%4,%5,%6,%7}, {%8,%9}, {%0,%1,%2,%3};"
        : "+f"(c[0]), "+f"(c[1]), "+f"(c[2]), "+f"(c[3])
        : "r"(a0), "r"(a1), "r"(a2), "r"(a3), "r"(b0), "r"(b1));
}
__device__ __forceinline__ void ldsm4(uint32_t& r0, uint32_t& r1,
                                      uint32_t& r2, uint32_t& r3, uint32_t addr) {
    asm volatile("ldmatrix.sync.aligned.m8n8.x4.shared.b16 {%0,%1,%2,%3}, [%4];"
                 : "=r"(r0), "=r"(r1), "=r"(r2), "=r"(r3) : "r"(addr));
}
__device__ __forceinline__ void cp_async16(uint32_t s, const void* g) {
    asm volatile("cp.async.ca.shared.global [%0], [%1], 16;" :: "r"(s), "l"(g));
}
__device__ __forceinline__ void cp_commit() { asm volatile("cp.async.commit_group;"); }
template<int N>
__device__ __forceinline__ void cp_wait() {
    asm volatile("cp.async.wait_group %0;" :: "n"(N));
}
__device__ __forceinline__ uint32_t smem_u32(const void* p) {
    return (uint32_t)__cvta_generic_to_shared(p);
}

// ---------------- fp16 tensor-core GEMM: C = A @ W^T + bias ----------------
#define HP 72
#define HSTG (128 * HP)               // halves per matrix per stage
#define GH_SMEM (4 * HSTG * 2)        // 73728 B

template<int MODE>
__global__ __launch_bounds__(256, 2)
void gemm_h(const float* __restrict__ bias)
{
    extern __shared__ __half hs[];
    const __half* A = (MODE == 0) ? g_xh : g_attnh;
    const __half* W = (MODE == 0) ? g_wqh : g_woh;

    const int tid  = threadIdx.x;
    const int w    = tid >> 5;
    const int lane = tid & 31;
    const int g    = lane >> 2;
    const int tig  = lane & 3;
    const int warpM = (w & 3) * 32;
    const int warpN = (w >> 2) * 64;
    const int bm = blockIdx.y * 128;
    const int bn = blockIdx.x * 128;

    float acc[2][8][4];
#pragma unroll
    for (int mt = 0; mt < 2; mt++)
#pragma unroll
        for (int nt = 0; nt < 8; nt++)
#pragma unroll
            for (int i = 0; i < 4; i++) acc[mt][nt][i] = 0.f;

    const uint32_t sb = smem_u32(hs);
    const int rit = (lane & 7) + ((lane >> 3) & 1) * 8;
    const int kh8 = (lane >> 4) * 8;

    auto load_stage = [&](int s) {
        const uint32_t abase = sb + (uint32_t)((s & 1) * 2 * HSTG) * 2u;
        const uint32_t bbase = abase + (uint32_t)HSTG * 2u;
#pragma unroll
        for (int i = 0; i < 4; i++) {
            const int o = tid + i * 256;
            const int row = o >> 3;
            const int c = o & 7;
            cp_async16(abase + (uint32_t)(row * HP + c * 8) * 2u,
                       A + (size_t)(bm + row) * DD + s * 64 + c * 8);
            cp_async16(bbase + (uint32_t)(row * HP + c * 8) * 2u,
                       W + (size_t)(bn + row) * DD + s * 64 + c * 8);
        }
        cp_commit();
    };

    load_stage(0);
    load_stage(1);

    uint32_t aRow[2][2], bRow[2][4];
#pragma unroll
    for (int bsel = 0; bsel < 2; bsel++) {
        const uint32_t abase = sb + (uint32_t)(bsel * 2 * HSTG) * 2u;
        const uint32_t bbase = abase + (uint32_t)HSTG * 2u;
#pragma unroll
        for (int mt = 0; mt < 2; mt++)
            aRow[bsel][mt] = abase + (uint32_t)((warpM + mt * 16 + rit) * HP + kh8) * 2u;
#pragma unroll
        for (int ng = 0; ng < 4; ng++)
            bRow[bsel][ng] = bbase + (uint32_t)((warpN + ng * 16 + rit) * HP + kh8) * 2u;
    }

    const int NS = DD / 64;   // 8
    for (int s = 0; s < NS; s++) {
        if (s + 1 < NS) cp_wait<1>(); else cp_wait<0>();
        __syncthreads();
        const int bsel = s & 1;
#pragma unroll
        for (int kk = 0; kk < 4; kk++) {
            const uint32_t koff = (uint32_t)(kk * 16) * 2u;
            uint32_t a[2][4];
#pragma unroll
            for (int mt = 0; mt < 2; mt++)
                ldsm4(a[mt][0], a[mt][1], a[mt][2], a[mt][3], aRow[bsel][mt] + koff);
#pragma unroll
            for (int ng = 0; ng < 4; ng++) {
                uint32_t r0, r1, r2, r3;
                ldsm4(r0, r1, r2, r3, bRow[bsel][ng] + koff);
#pragma unroll
                for (int mt = 0; mt < 2; mt++) {
                    mma_f16(acc[mt][2 * ng    ], a[mt][0], a[mt][1], a[mt][2], a[mt][3], r0, r2);
                    mma_f16(acc[mt][2 * ng + 1], a[mt][0], a[mt][1], a[mt][2], a[mt][3], r1, r3);
                }
            }
        }
        __syncthreads();
        if (s + 2 < NS) load_stage(s + 2);
    }

    // ---------------- epilogue ----------------
    const int nbase = bn + warpN;
    if (MODE == 0) {
        const int sec = nbase >> 9;
        const int colbase = nbase & 511;
        const int h = colbase >> 6;
        float* dst = (sec == 0) ? g_q : (sec == 1) ? g_k : g_v;
        float fac[2][2];
#pragma unroll
        for (int mt = 0; mt < 2; mt++)
#pragma unroll
            for (int rh = 0; rh < 2; rh++) {
                const int m = bm + warpM + mt * 16 + g + rh * 8;
                const float c = g_cum[m * HH + h];
                fac[mt][rh] = (sec == 0) ? __expf(c) * 0.125f
                            : (sec == 1) ? __expf(-c) : 1.f;
            }
#pragma unroll
        for (int mt = 0; mt < 2; mt++)
#pragma unroll
            for (int nt = 0; nt < 8; nt++) {
                const int ng = nbase + nt * 8 + tig * 2;
                const float b0 = bias[ng], b1 = bias[ng + 1];
                const int coln = colbase + nt * 8 + tig * 2;
#pragma unroll
                for (int rh = 0; rh < 2; rh++) {
                    const int m = bm + warpM + mt * 16 + g + rh * 8;
                    float v0 = acc[mt][nt][2 * rh    ] + b0;
                    float v1 = acc[mt][nt][2 * rh + 1] + b1;
                    if (sec < 2) {
                        v0 = (v0 > 0.f) ? (v0 + 1.f) : __expf(v0);
                        v1 = (v1 > 0.f) ? (v1 + 1.f) : __expf(v1);
                        v0 *= fac[mt][rh];
                        v1 *= fac[mt][rh];
                    }
                    float2 o; o.x = v0; o.y = v1;
                    *(float2*)(dst + (size_t)m * DD + coln) = o;
                }
            }
    } else {
#pragma unroll
        for (int mt = 0; mt < 2; mt++)
#pragma unroll
            for (int nt = 0; nt < 8; nt++) {
                const int ng = nbase + nt * 8 + tig * 2;
                const float b0 = bias[ng], b1 = bias[ng + 1];
#pragma unroll
                for (int rh = 0; rh < 2; rh++) {
                    const int m = bm + warpM + mt * 16 + g + rh * 8;
                    float2 o;
                    o.x = acc[mt][nt][2 * rh    ] + b0;
                    o.y = acc[mt][nt][2 * rh + 1] + b1;
                    *(float2*)(g_proj + (size_t)m * DD + ng) = o;
                }
            }
    }
}

// ---------------- prep: fp16 conversion (blocks 0..2559) + decay logits ------
#define NCVT 2560
__global__ __launch_bounds__(256)
void prep_kernel(const float* __restrict__ qkv_w, const float* __restrict__ out_w,
                 const float* __restrict__ x, const float* __restrict__ dw,
                 const float* __restrict__ db)
{
    if (blockIdx.x < NCVT) {
        const int u = blockIdx.x * 256 + threadIdx.x;    // 8-float unit
        const int NQ = 3 * DD * DD / 8;
        const int NO = DD * DD / 8;
        const float4* src;
        __half2* dst;
        int idx;
        if (u < NQ)           { src = (const float4*)qkv_w; dst = (__half2*)g_wqh; idx = u; }
        else if (u < NQ + NO) { src = (const float4*)out_w; dst = (__half2*)g_woh; idx = u - NQ; }
        else                  { src = (const float4*)x;     dst = (__half2*)g_xh;  idx = u - NQ - NO; }
        float4 v0 = src[2 * idx], v1 = src[2 * idx + 1];
        dst[4 * idx + 0] = __floats2half2_rn(v0.x, v0.y);
        dst[4 * idx + 1] = __floats2half2_rn(v0.z, v0.w);
        dst[4 * idx + 2] = __floats2half2_rn(v1.x, v1.y);
        dst[4 * idx + 3] = __floats2half2_rn(v1.z, v1.w);
        return;
    }
    const int m = blockIdx.x - NCVT;
    const int h = threadIdx.x >> 5;
    const int lane = threadIdx.x & 31;
    const float* xr = x + (size_t)m * DD;
    const float* wr = dw + h * DD;
    float s = 0.f;
    for (int k = lane * 4; k < DD; k += 128) {
        float4 xv = *(const float4*)(xr + k);
        float4 wv = *(const float4*)(wr + k);
        s += xv.x * wv.x + xv.y * wv.y + xv.z * wv.z + xv.w * wv.w;
    }
#pragma unroll
    for (int off = 16; off; off >>= 1) s += __shfl_xor_sync(0xffffffffu, s, off);
    if (lane == 0) {
        float logit = s + db[h];
        float lam = 0.9f + 0.1f / (1.f + expf(-logit));
        g_loglam[m * HH + h] = logf(lam);
    }
}

// ---------------- cumsum of log-lambda along L ----------------
__global__ __launch_bounds__(256)
void cumsum_kernel()
{
    const int b = blockIdx.x >> 3;
    const int h = blockIdx.x & 7;
    const int tid = threadIdx.x;
    float vals[16];
    float s = 0.f;
    const int base = (b * LL + tid * 16) * HH + h;
#pragma unroll
    for (int i = 0; i < 16; i++) { s += g_loglam[base + i * HH]; vals[i] = s; }
    __shared__ float ts[256];
    ts[tid] = s;
    __syncthreads();
    for (int off = 1; off < 256; off <<= 1) {
        float v = (tid >= off) ? ts[tid - off] : 0.f;
        __syncthreads();
        ts[tid] += v;
        __syncthreads();
    }
    const float prev = (tid > 0) ? ts[tid - 1] : 0.f;
#pragma unroll
    for (int i = 0; i < 16; i++) {
        float c = prev + vals[i];
        c = fminf(50.f, fmaxf(-50.f, c));
        g_cum[base + i * HH] = c;
    }
}

// ---------------- per-chunk transposed KV state + k-sum (tf32 mma) ----------
// Row-major staging; transposed-operand fragments assembled via swapped
// scalar-LDS indexing (no smem transpose pass).
#define CP2 68
__global__ __launch_bounds__(128)
void chunkstate_mma()
{
    __shared__ float ks[64 * CP2];
    __shared__ float vs[64 * CP2];
    const int c = blockIdx.x & (NC - 1);
    const int h = (blockIdx.x >> 6) & 7;
    const int b = blockIdx.x >> 9;
    const int bh = b * HH + h;
    const int tid = threadIdx.x;
    const int w = tid >> 5;
    const int lane = tid & 31;
    const int g = lane >> 2;
    const int tig = lane & 3;
    const int rowbase = b * LL + c * CC;

#pragma unroll
    for (int it = 0; it < 8; it++) {
        int idx4 = tid + it * 128;
        int t = idx4 >> 4;
        int e4 = (idx4 & 15) << 2;
        size_t gidx = (size_t)(rowbase + t) * DD + h * EE + e4;
        *(float4*)&ks[t * CP2 + e4] = *(const float4*)(g_k + gidx);
        *(float4*)&vs[t * CP2 + e4] = *(const float4*)(g_v + gidx);
    }
    __syncthreads();

    const int f0 = w * 16;
    float acc[8][4];
#pragma unroll
    for (int nt = 0; nt < 8; nt++)
#pragma unroll
        for (int i = 0; i < 4; i++) acc[nt][i] = 0.f;

#pragma unroll
    for (int kk = 0; kk < 8; kk++) {
        const int k0 = kk * 8;
        // A = v^T : A[m][k] = vs[(k0+k)*CP2 + f0+m]
        uint32_t a[4];
        a[0] = f2tf32(vs[(k0 + tig    ) * CP2 + f0 + g    ]);
        a[1] = f2tf32(vs[(k0 + tig    ) * CP2 + f0 + g + 8]);
        a[2] = f2tf32(vs[(k0 + tig + 4) * CP2 + f0 + g    ]);
        a[3] = f2tf32(vs[(k0 + tig + 4) * CP2 + f0 + g + 8]);
#pragma unroll
        for (int nt = 0; nt < 8; nt++) {
            // B = k^T : B[n][k] = ks[(k0+k)*CP2 + nt*8+n]
            uint32_t b0 = f2tf32(ks[(k0 + tig    ) * CP2 + nt * 8 + g]);
            uint32_t b1 = f2tf32(ks[(k0 + tig + 4) * CP2 + nt * 8 + g]);
            mma_tf32(acc[nt], a, b0, b1);
        }
    }

    const size_t sbx = ((size_t)bh * NC + c) * (EE * EE);
#pragma unroll
    for (int nt = 0; nt < 8; nt++) {
        const int e0 = nt * 8 + tig * 2;
        float2 s0; s0.x = acc[nt][0]; s0.y = acc[nt][1];
        float2 s1; s1.x = acc[nt][2]; s1.y = acc[nt][3];
        *(float2*)(g_state + sbx + (f0 + g    ) * EE + e0) = s0;
        *(float2*)(g_state + sbx + (f0 + g + 8) * EE + e0) = s1;
    }
    if (tid < 64) {
        float z = 0.f;
#pragma unroll 8
        for (int t = 0; t < CC; t++) z += ks[t * CP2 + tid];
        g_zstate[(bh * NC + c) * EE + tid] = z;
    }
}

// ---------------- exclusive scan over chunks ----------------
__global__ __launch_bounds__(256)
void statescan_kernel()
{
    const int bh = blockIdx.x >> 4;
    const int split = blockIdx.x & 15;
    const int elem = split * 256 + threadIdx.x;
    size_t base = (size_t)bh * NC * EE * EE + elem;
    float run = 0.f;
#pragma unroll 4
    for (int c = 0; c < NC; c++) {
        float v = g_state[base + (size_t)c * EE * EE];
        g_state[base + (size_t)c * EE * EE] = run;
        run += v;
    }
    if (split == 0 && threadIdx.x < 64) {
        size_t zb = (size_t)bh * NC * EE + threadIdx.x;
        float r = 0.f;
        for (int c = 0; c < NC; c++) {
            float v = g_zstate[zb + (size_t)c * EE];
            g_zstate[zb + (size_t)c * EE] = r;
            r += v;
        }
    }
}

// ---------------- intra-chunk attention (tf32 mma) ----------------
#define IP 68
#define OQ 0
#define OK (64*IP)
#define OP (2*64*IP)
#define OS (3*64*IP)
#define OV (4*64*IP)
#define OZ (OV + 64*IP)
#define ODEN (OZ + 64)
#define ISMF (ODEN + 64)

__global__ __launch_bounds__(256)
void intra_mma()
{
    extern __shared__ float sm[];
    const int c = blockIdx.x & (NC - 1);
    const int h = (blockIdx.x >> 6) & 7;
    const int b = blockIdx.x >> 9;
    const int bh = b * HH + h;
    const int tid = threadIdx.x;
    const int w = tid >> 5;
    const int lane = tid & 31;
    const int g = lane >> 2;
    const int tig = lane & 3;
    const int rowbase = b * LL + c * CC;
    const size_t sbx = ((size_t)bh * NC + c) * (EE * EE);

#pragma unroll
    for (int it = 0; it < 4; it++) {
        int idx4 = tid + it * 256;
        int t = idx4 >> 4;
        int e4 = (idx4 & 15) << 2;
        size_t gidx = (size_t)(rowbase + t) * DD + h * EE + e4;
        *(float4*)&sm[OQ + t * IP + e4] = *(const float4*)(g_q + gidx);
        *(float4*)&sm[OK + t * IP + e4] = *(const float4*)(g_k + gidx);
        *(float4*)&sm[OV + t * IP + e4] = *(const float4*)(g_v + gidx);
        *(float4*)&sm[OS + t * IP + e4] = *(const float4*)(g_state + sbx + idx4 * 4);
    }
    if (tid < 64) sm[OZ + tid] = g_zstate[(bh * NC + c) * EE + tid];
    __syncthreads();

    const int wm = (w & 3) * 16;
    const int wn = (w >> 2) * 32;

    // phase 1: P = q k^T, causal mask; fully-masked warp tiles skip the MMAs
    if (wn > wm + 15) {
        const float2 z2 = make_float2(0.f, 0.f);
#pragma unroll
        for (int nt = 0; nt < 4; nt++) {
            const int scol = wn + nt * 8 + tig * 2;
            *(float2*)&sm[OP + (wm + g    ) * IP + scol] = z2;
            *(float2*)&sm[OP + (wm + g + 8) * IP + scol] = z2;
        }
    } else {
        float pacc[4][4];
#pragma unroll
        for (int nt = 0; nt < 4; nt++)
#pragma unroll
            for (int i = 0; i < 4; i++) pacc[nt][i] = 0.f;
#pragma unroll
        for (int kk = 0; kk < 8; kk++) {
            const int k0 = kk * 8;
            uint32_t a[4];
            a[0] = f2tf32(sm[OQ + (wm + g    ) * IP + k0 + tig    ]);
            a[1] = f2tf32(sm[OQ + (wm + g + 8) * IP + k0 + tig    ]);
            a[2] = f2tf32(sm[OQ + (wm + g    ) * IP + k0 + tig + 4]);
            a[3] = f2tf32(sm[OQ + (wm + g + 8) * IP + k0 + tig + 4]);
#pragma unroll
            for (int nt = 0; nt < 4; nt++) {
                uint32_t b0 = f2tf32(sm[OK + (wn + nt * 8 + g) * IP + k0 + tig    ]);
                uint32_t b1 = f2tf32(sm[OK + (wn + nt * 8 + g) * IP + k0 + tig + 4]);
                mma_tf32(pacc[nt], a, b0, b1);
            }
        }
#pragma unroll
        for (int nt = 0; nt < 4; nt++) {
            const int scol = wn + nt * 8 + tig * 2;
            const int r0 = wm + g, r1 = wm + g + 8;
            float2 p0, p1;
            p0.x = (scol     <= r0) ? pacc[nt][0] : 0.f;
            p0.y = (scol + 1 <= r0) ? pacc[nt][1] : 0.f;
            p1.x = (scol     <= r1) ? pacc[nt][2] : 0.f;
            p1.y = (scol + 1 <= r1) ? pacc[nt][3] : 0.f;
            *(float2*)&sm[OP + r0 * IP + scol] = p0;
            *(float2*)&sm[OP + r1 * IP + scol] = p1;
        }
    }
    __syncthreads();

    // phase 2: denominators
    if (tid < 64) {
        const int t = tid;
        float s = 0.f;
#pragma unroll 8
        for (int s2 = 0; s2 < CC; s2++) s += sm[OP + t * IP + s2];
#pragma unroll 8
        for (int e = 0; e < EE; e++) s += sm[OQ + t * IP + e] * sm[OZ + e];
        sm[ODEN + t] = 1.f / (s + 1e-6f);
    }
    __syncthreads();

    // phase 3: num = P @ v + q @ S_T; out = num * rden -> fp16 g_attnh
    {
        float acc[4][4];
#pragma unroll
        for (int nt = 0; nt < 4; nt++)
#pragma unroll
            for (int i = 0; i < 4; i++) acc[nt][i] = 0.f;

#pragma unroll
        for (int kk = 0; kk < 8; kk++) {
            const int k0 = kk * 8;
            uint32_t a[4];
            a[0] = f2tf32(sm[OP + (wm + g    ) * IP + k0 + tig    ]);
            a[1] = f2tf32(sm[OP + (wm + g + 8) * IP + k0 + tig    ]);
            a[2] = f2tf32(sm[OP + (wm + g    ) * IP + k0 + tig + 4]);
            a[3] = f2tf32(sm[OP + (wm + g + 8) * IP + k0 + tig + 4]);
#pragma unroll
            for (int nt = 0; nt < 4; nt++) {
                // B = v^T : B[n][k] = v[k][n] = sm[OV + (k0+k)*IP + wn+nt*8+n]
                uint32_t b0 = f2tf32(sm[OV + (k0 + tig    ) * IP + wn + nt * 8 + g]);
                uint32_t b1 = f2tf32(sm[OV + (k0 + tig + 4) * IP + wn + nt * 8 + g]);
                mma_tf32(acc[nt], a, b0, b1);
            }
        }
#pragma unroll
        for (int kk = 0; kk < 8; kk++) {
            const int k0 = kk * 8;
            uint32_t a[4];
            a[0] = f2tf32(sm[OQ + (wm + g    ) * IP + k0 + tig    ]);
            a[1] = f2tf32(sm[OQ + (wm + g + 8) * IP + k0 + tig    ]);
            a[2] = f2tf32(sm[OQ + (wm + g    ) * IP + k0 + tig + 4]);
            a[3] = f2tf32(sm[OQ + (wm + g + 8) * IP + k0 + tig + 4]);
#pragma unroll
            for (int nt = 0; nt < 4; nt++) {
                uint32_t b0 = f2tf32(sm[OS + (wn + nt * 8 + g) * IP + k0 + tig    ]);
                uint32_t b1 = f2tf32(sm[OS + (wn + nt * 8 + g) * IP + k0 + tig + 4]);
                mma_tf32(acc[nt], a, b0, b1);
            }
        }

        const float rd0 = sm[ODEN + wm + g];
        const float rd1 = sm[ODEN + wm + g + 8];
#pragma unroll
        for (int nt = 0; nt < 4; nt++) {
            const int colb = h * EE + wn + nt * 8 + tig * 2;
            *(__half2*)(g_attnh + (size_t)(rowbase + wm + g    ) * DD + colb) =
                __floats2half2_rn(acc[nt][0] * rd0, acc[nt][1] * rd0);
            *(__half2*)(g_attnh + (size_t)(rowbase + wm + g + 8) * DD + colb) =
                __floats2half2_rn(acc[nt][2] * rd1, acc[nt][3] * rd1);
        }
    }
}

// ---------------- RMSNorm ----------------
__global__ __launch_bounds__(128)
void rmsnorm_kernel(const float* __restrict__ scale, float* __restrict__ out)
{
    const int m = blockIdx.x;
    const int tid = threadIdx.x;
    float4 v = *(const float4*)(g_proj + (size_t)m * DD + tid * 4);
    float ss = v.x * v.x + v.y * v.y + v.z * v.z + v.w * v.w;
#pragma unroll
    for (int off = 16; off; off >>= 1) ss += __shfl_xor_sync(0xffffffffu, ss, off);
    __shared__ float ws[4];
    if ((tid & 31) == 0) ws[tid >> 5] = ss;
    __syncthreads();
    float tot = ws[0] + ws[1] + ws[2] + ws[3];
    float rn = rsqrtf(tot * (1.f / DD) + 1e-8f);
    float4 sc = *(const float4*)(scale + tid * 4);
    float4 o;
    o.x = v.x * rn * sc.x; o.y = v.y * rn * sc.y;
    o.z = v.z * rn * sc.z; o.w = v.w * rn * sc.w;
    *(float4*)(out + (size_t)m * DD + tid * 4) = o;
}

// ---------------- launch ----------------
extern "C" void kernel_launch(void* const* d_in, const int* in_sizes, int n_in,
                              void* d_out, int out_size)
{
    const float* x          = (const float*)d_in[0];
    const float* qkv_w      = (const float*)d_in[1];
    const float* qkv_b      = (const float*)d_in[2];
    const float* out_w      = (const float*)d_in[3];
    const float* out_b      = (const float*)d_in[4];
    const float* decay_w    = (const float*)d_in[5];
    const float* decay_b    = (const float*)d_in[6];
    const float* norm_scale = (const float*)d_in[7];
    float* out = (float*)d_out;

    cudaFuncSetAttribute(gemm_h<0>, cudaFuncAttributeMaxDynamicSharedMemorySize, GH_SMEM);
    cudaFuncSetAttribute(gemm_h<1>, cudaFuncAttributeMaxDynamicSharedMemorySize, GH_SMEM);
    const int ism = ISMF * (int)sizeof(float);
    cudaFuncSetAttribute(intra_mma, cudaFuncAttributeMaxDynamicSharedMemorySize, ism);

    prep_kernel<<<NCVT + MM, 256>>>(qkv_w, out_w, x, decay_w, decay_b);  // #1
    cumsum_kernel<<<BB * HH, 256>>>();                                   // #2
    gemm_h<0><<<dim3(12, 64), 256, GH_SMEM>>>(qkv_b);                    // #3
    chunkstate_mma<<<BB * HH * NC, 128>>>();                             // #4 <- capture
    statescan_kernel<<<BB * HH * 16, 256>>>();                           // #5
    intra_mma<<<BB * HH * NC, 256, ism>>>();                             // #6
    gemm_h<1><<<dim3(4, 64), 256, GH_SMEM>>>(out_b);                     // #7
    rmsnorm_kernel<<<MM, 128>>>(norm_scale, out);                        // #8
}